// round 12
// baseline (speedup 1.0000x reference)
#include <cuda_runtime.h>
#include <math.h>

#define N_RES  8192
#define N_IN   128
#define BATCH  16
#define LEAK   0.9f

#define NCB     256                 // coarse bins (32 rows each)
#define CCAP    28672               // per-bin capacity (Poisson 26214, +15 sigma)
#define DEPTH_C 64                  // coarse staging depth (mean 32/round)
#define NCH     152                 // coarse stream chunks (1/SM)
#define TC      8192                // entries per coarse round (1024 thr x 8)

#define NSEG    2                   // fuse segments per bin (grid = 512)
#define TF2     2048                // entries per fuse round (256 producer thr x 8)
#define DEPTH2  104                 // staging depth per row per round (mean 64)

#define COARSE_SMEM (NCB * DEPTH_C * (int)sizeof(float2))   // 128 KB
#define FUSE_SMEM   (2 * 32 * DEPTH2 * (int)sizeof(float2)) // 53.25 KB

// ---------------------------------------------------------------------------
// Scratch (allocation-free __device__ globals)
__device__ __align__(16) float g_z[N_RES * BATCH];          // bias + input + reservoir acc
__device__ __align__(16) float g_state_T[N_RES * BATCH];    // [row][batch]
__device__ __align__(16) float g_x_T[N_IN * BATCH];
__device__ unsigned g_ccur[NCB];
__device__ unsigned g_done[NCB];
__device__ __align__(16) float2 g_cbucket[(size_t)NCB * CCAP];  // 58.7 MB

__device__ __forceinline__ void red_add_v4(float* p, float a, float b, float c, float d) {
    asm volatile("red.global.add.v4.f32 [%0], {%1,%2,%3,%4};"
                 :: "l"(p), "f"(a), "f"(b), "f"(c), "f"(d) : "memory");
}
__device__ __forceinline__ void red_add_f32(float* p, float a) {
    asm volatile("red.global.add.f32 [%0], %1;" :: "l"(p), "f"(a) : "memory");
}

// ---------------------------------------------------------------------------
// Kernel 1: init z with biases, zero cursors/counters, transpose state and x.
__global__ void k_init(const float* __restrict__ state,
                       const float* __restrict__ x,
                       const float* __restrict__ res_bias,
                       const float* __restrict__ in_bias) {
    int i = blockIdx.x * blockDim.x + threadIdx.x;
    if (i < N_RES * BATCH) {
        int r = i >> 4;
        int b = i & (BATCH - 1);
        g_z[i]       = res_bias[r] + in_bias[r];
        g_state_T[i] = state[b * N_RES + r];
    }
    if (i < N_IN * BATCH) {
        int r = i >> 4;
        int b = i & (BATCH - 1);
        g_x_T[i] = x[b * N_IN + r];
    }
    if (i < NCB) { g_ccur[i] = 0; g_done[i] = 0; }
}

// ---------------------------------------------------------------------------
// Kernel 2: input SpMM (small: ~105K entries).
__global__ void k_in_spmm(const float* __restrict__ vals,
                          const int*   __restrict__ rows,
                          const int*   __restrict__ cols,
                          int nnz) {
    int i = blockIdx.x * blockDim.x + threadIdx.x;
    if (i >= nnz) return;
    float v = vals[i];
    int r = rows[i];
    int c = cols[i];
    const float4* s = reinterpret_cast<const float4*>(g_x_T + c * BATCH);
    float4 s0 = s[0], s1 = s[1], s2 = s[2], s3 = s[3];
    float* zp = g_z + r * BATCH;
    red_add_v4(zp + 0,  v * s0.x, v * s0.y, v * s0.z, v * s0.w);
    red_add_v4(zp + 4,  v * s1.x, v * s1.y, v * s1.z, v * s1.w);
    red_add_v4(zp + 8,  v * s2.x, v * s2.y, v * s2.z, v * s2.w);
    red_add_v4(zp + 12, v * s3.x, v * s3.y, v * s3.z, v * s3.w);
}

// ---------------------------------------------------------------------------
// Kernel 3: coarse partition by row-block (r>>5), smem staging, coalesced
// flush with parallel cursor reservation (proven R10/R11).
__global__ void __launch_bounds__(1024) k_coarse(const float* __restrict__ vals,
                                                 const int*   __restrict__ rows,
                                                 const int*   __restrict__ cols,
                                                 int nnz, int csz) {
    extern __shared__ float2 sbuf[];             // NCB * DEPTH_C
    __shared__ unsigned scnt[NCB];
    __shared__ unsigned sbase[NCB];
    int tid  = threadIdx.x;
    int w    = tid >> 5;
    int lane = tid & 31;
    int start = blockIdx.x * csz;
    int end   = min(nnz, start + csz);

    for (int base = start; base < end; base += TC) {
        if (tid < NCB) scnt[tid] = 0;
        __syncthreads();

        int i0 = base + tid * 8;
        if (base + TC <= end) {
            float4 v0 = *(const float4*)(vals + i0);
            float4 v1 = *(const float4*)(vals + i0 + 4);
            int4   r0 = *(const int4*)(rows + i0);
            int4   r1 = *(const int4*)(rows + i0 + 4);
            int4   c0 = *(const int4*)(cols + i0);
            int4   c1 = *(const int4*)(cols + i0 + 4);
            float vv[8] = {v0.x, v0.y, v0.z, v0.w, v1.x, v1.y, v1.z, v1.w};
            int   rr[8] = {r0.x, r0.y, r0.z, r0.w, r1.x, r1.y, r1.z, r1.w};
            int   cc[8] = {c0.x, c0.y, c0.z, c0.w, c1.x, c1.y, c1.z, c1.w};
#pragma unroll
            for (int k = 0; k < 8; k++) {
                int bin = rr[k] >> 5;
                unsigned pos = atomicAdd(&scnt[bin], 1u);
                float2 e = make_float2(vv[k],
                    __int_as_float(cc[k] | ((rr[k] & 31) << 13)));
                if (pos < DEPTH_C) sbuf[bin * DEPTH_C + pos] = e;
                else {                                   // ~never
                    unsigned p = atomicAdd(&g_ccur[bin], 1u);
                    if (p < CCAP) g_cbucket[(size_t)bin * CCAP + p] = e;
                }
            }
        } else {
            for (int k = 0; k < 8; k++) {
                int i = i0 + k;
                if (i < end) {
                    int r = rows[i], c = cols[i];
                    int bin = r >> 5;
                    unsigned pos = atomicAdd(&scnt[bin], 1u);
                    float2 e = make_float2(vals[i],
                        __int_as_float(c | ((r & 31) << 13)));
                    if (pos < DEPTH_C) sbuf[bin * DEPTH_C + pos] = e;
                    else {
                        unsigned p = atomicAdd(&g_ccur[bin], 1u);
                        if (p < CCAP) g_cbucket[(size_t)bin * CCAP + p] = e;
                    }
                }
            }
        }
        __syncthreads();

        if (tid < NCB) {
            unsigned c = min(scnt[tid], (unsigned)DEPTH_C);
            sbase[tid] = c ? atomicAdd(&g_ccur[tid], c) : 0u;
        }
        __syncthreads();

        for (int b = w * 8; b < w * 8 + 8; b++) {
            unsigned cnt = min(scnt[b], (unsigned)DEPTH_C);
            if (cnt == 0) continue;
            size_t dst = (size_t)b * CCAP + sbase[b];
            if (lane < cnt)
                g_cbucket[dst + lane] = sbuf[b * DEPTH_C + lane];
            if (cnt > 32 && lane + 32 < cnt)
                g_cbucket[dst + lane + 32] = sbuf[b * DEPTH_C + lane + 32];
        }
        __syncthreads();
    }
}

// ---------------------------------------------------------------------------
__device__ __forceinline__ float drain_row(const float2* __restrict__ row,
                                           int m, int half, int b) {
    float a = 0.0f;
    int j = half;
    for (; j + 6 < m; j += 8) {
        float2 e0 = row[j];
        float2 e1 = row[j + 2];
        float2 e2 = row[j + 4];
        float2 e3 = row[j + 6];
        float s0 = g_state_T[(__float_as_int(e0.y) & 8191) * BATCH + b];
        float s1 = g_state_T[(__float_as_int(e1.y) & 8191) * BATCH + b];
        float s2 = g_state_T[(__float_as_int(e2.y) & 8191) * BATCH + b];
        float s3 = g_state_T[(__float_as_int(e3.y) & 8191) * BATCH + b];
        a = fmaf(e0.x, s0, a);
        a = fmaf(e1.x, s1, a);
        a = fmaf(e2.x, s2, a);
        a = fmaf(e3.x, s3, a);
    }
    for (; j < m; j += 2) {
        float2 e = row[j];
        a = fmaf(e.x, g_state_T[(__float_as_int(e.y) & 8191) * BATCH + b], a);
    }
    return a;
}

// ---------------------------------------------------------------------------
// Kernel 4 (ncu slot): warp-specialized fused refine+gather+epilogue.
// Grid 512 = (bin, segment). Warps 0-7 produce (stream + stage into double
// buffer); warps 8-15 consume (drain 4 rows each into register accumulators).
// Stage latency hides under drain. Last segment-block runs the erf epilogue.
__global__ void __launch_bounds__(512, 4) k_fuse(float* __restrict__ out) {
    extern __shared__ float2 dyn[];              // 2 x 32 x DEPTH2
    __shared__ unsigned scnt[2][32];
    __shared__ unsigned sdone;
    int tid  = threadIdx.x;
    int w    = tid >> 5;
    int lane = tid & 31;
    int half = lane >> 4;
    int b    = lane & 15;
    int cb   = blockIdx.x >> 1;
    int seg  = blockIdx.x & 1;

    int cnt = min(g_ccur[cb], (unsigned)CCAP);
    int s_beg = seg ? (cnt >> 1) : 0;
    int s_end = seg ? cnt : (cnt >> 1);
    const float2* __restrict__ src = g_cbucket + (size_t)cb * CCAP;
    int nrounds = (s_end - s_beg + TF2 - 1) / TF2;

    if (tid < 64) ((unsigned*)scnt)[tid] = 0;
    __syncthreads();

    float acc0 = 0.0f, acc1 = 0.0f, acc2 = 0.0f, acc3 = 0.0f;

    for (int rd = 0; rd <= nrounds; rd++) {
        if (w < 8) {
            // ---- producers: stage round rd into buffer rd&1 ----
            if (rd < nrounds) {
                int p = rd & 1;
                float2* bufp = dyn + p * (32 * DEPTH2);
                int base = s_beg + rd * TF2;
                int n = min(TF2, s_end - base);
#pragma unroll
                for (int k = 0; k < 8; k++) {
                    int idx = tid + (k << 8);
                    if (idx < n) {
                        float2 e = src[base + idx];
                        int rl = (__float_as_int(e.y) >> 13) & 31;
                        unsigned pos = atomicAdd(&scnt[p][rl], 1u);
                        if (pos < DEPTH2) {
                            bufp[rl * DEPTH2 + pos] = e;
                        } else {                 // ~never: direct z accumulation
                            int c = __float_as_int(e.y) & 8191;
                            float v = e.x;
                            const float4* s4 =
                                reinterpret_cast<const float4*>(g_state_T + c * BATCH);
                            float4 s0 = s4[0], s1 = s4[1], s2 = s4[2], s3 = s4[3];
                            float* zp = g_z + ((cb << 5) | rl) * BATCH;
                            red_add_v4(zp + 0,  v*s0.x, v*s0.y, v*s0.z, v*s0.w);
                            red_add_v4(zp + 4,  v*s1.x, v*s1.y, v*s1.z, v*s1.w);
                            red_add_v4(zp + 8,  v*s2.x, v*s2.y, v*s2.z, v*s2.w);
                            red_add_v4(zp + 12, v*s3.x, v*s3.y, v*s3.z, v*s3.w);
                        }
                    }
                }
            }
        } else {
            // ---- consumers: drain round rd-1 from buffer (rd-1)&1 ----
            if (rd >= 1) {
                int q = (rd - 1) & 1;
                float2* bufq = dyn + q * (32 * DEPTH2);
                int rl0 = (w - 8) << 2;
                int m0 = min(scnt[q][rl0 + 0], (unsigned)DEPTH2);
                int m1 = min(scnt[q][rl0 + 1], (unsigned)DEPTH2);
                int m2 = min(scnt[q][rl0 + 2], (unsigned)DEPTH2);
                int m3 = min(scnt[q][rl0 + 3], (unsigned)DEPTH2);
                __syncwarp();
                if (lane < 4) scnt[q][rl0 + lane] = 0;   // recycle for round rd+1
                acc0 += drain_row(bufq + (rl0 + 0) * DEPTH2, m0, half, b);
                acc1 += drain_row(bufq + (rl0 + 1) * DEPTH2, m1, half, b);
                acc2 += drain_row(bufq + (rl0 + 2) * DEPTH2, m2, half, b);
                acc3 += drain_row(bufq + (rl0 + 3) * DEPTH2, m3, half, b);
            }
        }
        __syncthreads();
    }

    // ---- consumers flush 32-row partials into g_z ----
    if (w >= 8) {
        acc0 += __shfl_xor_sync(0xffffffffu, acc0, 16);
        acc1 += __shfl_xor_sync(0xffffffffu, acc1, 16);
        acc2 += __shfl_xor_sync(0xffffffffu, acc2, 16);
        acc3 += __shfl_xor_sync(0xffffffffu, acc3, 16);
        if (lane < BATCH) {
            int r0 = (cb << 5) | ((w - 8) << 2);
            red_add_f32(g_z + (r0 + 0) * BATCH + lane, acc0);
            red_add_f32(g_z + (r0 + 1) * BATCH + lane, acc1);
            red_add_f32(g_z + (r0 + 2) * BATCH + lane, acc2);
            red_add_f32(g_z + (r0 + 3) * BATCH + lane, acc3);
        }
    }
    __syncthreads();

    // ---- completion counter: last segment-block runs the epilogue ----
    if (tid == 0) {
        __threadfence();
        sdone = atomicAdd(&g_done[cb], 1u);
    }
    __syncthreads();
    if (sdone == NSEG - 1) {
        __threadfence();
        int i = (cb << 9) | tid;                 // row-major index into bin's 512 outs
        float z = g_z[i];
        float s = g_state_T[i];                  // state[b][r] transposed
        int r = i >> 4;
        int bb = i & 15;
        out[bb * N_RES + r] = (1.0f - LEAK) * s + LEAK * erff(z);
    }
}

// ---------------------------------------------------------------------------
extern "C" void kernel_launch(void* const* d_in, const int* in_sizes, int n_in,
                              void* d_out, int out_size) {
    const float* state    = (const float*)d_in[0];
    const float* x        = (const float*)d_in[1];
    const float* res_vals = (const float*)d_in[2];
    const int*   res_rows = (const int*)  d_in[3];
    const int*   res_cols = (const int*)  d_in[4];
    const float* res_bias = (const float*)d_in[5];
    const float* in_vals  = (const float*)d_in[6];
    const int*   in_rows  = (const int*)  d_in[7];
    const int*   in_cols  = (const int*)  d_in[8];
    const float* in_bias  = (const float*)d_in[9];
    float* out = (float*)d_out;

    int res_nnz = in_sizes[2];
    int in_nnz  = in_sizes[6];
    int csz = ((res_nnz + NCH - 1) / NCH + 7) & ~7;

    static int smem_set = 0;
    if (!smem_set) {
        cudaFuncSetAttribute(k_coarse, cudaFuncAttributeMaxDynamicSharedMemorySize, COARSE_SMEM);
        cudaFuncSetAttribute(k_fuse,   cudaFuncAttributeMaxDynamicSharedMemorySize, FUSE_SMEM);
        smem_set = 1;
    }

    // Launch order: slot 4 (ncu capture) = k_fuse.
    k_init<<<(N_RES * BATCH + 255) / 256, 256>>>(state, x, res_bias, in_bias);

    k_in_spmm<<<(in_nnz + 255) / 256, 256>>>(in_vals, in_rows, in_cols, in_nnz);

    k_coarse<<<NCH, 1024, COARSE_SMEM>>>(res_vals, res_rows, res_cols, res_nnz, csz);

    k_fuse<<<NCB * NSEG, 512, FUSE_SMEM>>>(out);
}

// round 13
// speedup vs baseline: 1.0617x; 1.0617x over previous
#include <cuda_runtime.h>
#include <math.h>

#define N_RES  8192
#define N_IN   128
#define BATCH  16
#define LEAK   0.9f

#define NCB     256                 // coarse bins (32 rows each)
#define CCAP    28672               // per-bin capacity
#define DEPTH_C 48                  // coarse staging depth (mean 32/round)
#define NCH     304                 // coarse stream chunks (2/SM)
#define TC      8192                // entries per coarse round (1024 thr x 8)

#define NSEG    2                   // fuse segments per bin (grid = 512)
#define DEPTH_F 192                 // fuse staging depth per row per round
#define TF      4096                // entries per fuse round (512 thr x 8)

#define COARSE_SMEM (NCB * DEPTH_C * (int)sizeof(float2))   // 96 KB
#define FUSE_SMEM   (32 * DEPTH_F * (int)sizeof(float2))    // 48 KB

// ---------------------------------------------------------------------------
// Scratch (allocation-free __device__ globals)
__device__ __align__(16) float g_z[N_RES * BATCH];          // bias + input + reservoir acc
__device__ __align__(16) float g_state_T[N_RES * BATCH];    // [row][batch]
__device__ __align__(16) float g_x_T[N_IN * BATCH];
__device__ unsigned g_ccur[NCB];
__device__ unsigned g_done[NCB];
__device__ __align__(16) float2 g_cbucket[(size_t)NCB * CCAP];  // 58.7 MB

__device__ __forceinline__ void red_add_v4(float* p, float a, float b, float c, float d) {
    asm volatile("red.global.add.v4.f32 [%0], {%1,%2,%3,%4};"
                 :: "l"(p), "f"(a), "f"(b), "f"(c), "f"(d) : "memory");
}
__device__ __forceinline__ void red_add_f32(float* p, float a) {
    asm volatile("red.global.add.f32 [%0], %1;" :: "l"(p), "f"(a) : "memory");
}

// ---------------------------------------------------------------------------
// Kernel 1: init z with biases, zero cursors/counters, transpose state and x.
__global__ void k_init(const float* __restrict__ state,
                       const float* __restrict__ x,
                       const float* __restrict__ res_bias,
                       const float* __restrict__ in_bias) {
    int i = blockIdx.x * blockDim.x + threadIdx.x;
    if (i < N_RES * BATCH) {
        int r = i >> 4;
        int b = i & (BATCH - 1);
        g_z[i]       = res_bias[r] + in_bias[r];
        g_state_T[i] = state[b * N_RES + r];
    }
    if (i < N_IN * BATCH) {
        int r = i >> 4;
        int b = i & (BATCH - 1);
        g_x_T[i] = x[b * N_IN + r];
    }
    if (i < NCB) { g_ccur[i] = 0; g_done[i] = 0; }
}

// ---------------------------------------------------------------------------
// Kernel 2: input SpMM (small: ~105K entries).
__global__ void k_in_spmm(const float* __restrict__ vals,
                          const int*   __restrict__ rows,
                          const int*   __restrict__ cols,
                          int nnz) {
    int i = blockIdx.x * blockDim.x + threadIdx.x;
    if (i >= nnz) return;
    float v = vals[i];
    int r = rows[i];
    int c = cols[i];
    const float4* s = reinterpret_cast<const float4*>(g_x_T + c * BATCH);
    float4 s0 = s[0], s1 = s[1], s2 = s[2], s3 = s[3];
    float* zp = g_z + r * BATCH;
    red_add_v4(zp + 0,  v * s0.x, v * s0.y, v * s0.z, v * s0.w);
    red_add_v4(zp + 4,  v * s1.x, v * s1.y, v * s1.z, v * s1.w);
    red_add_v4(zp + 8,  v * s2.x, v * s2.y, v * s2.z, v * s2.w);
    red_add_v4(zp + 12, v * s3.x, v * s3.y, v * s3.z, v * s3.w);
}

// ---------------------------------------------------------------------------
// Kernel 3: coarse partition (r>>5) with smem staging; 2 blocks/SM.
__device__ __forceinline__ void cplace(float v, int r, int c,
                                       unsigned* scnt, float2* sbuf) {
    int bin = r >> 5;
    unsigned pos = atomicAdd(&scnt[bin], 1u);
    float2 e = make_float2(v, __int_as_float(c | ((r & 31) << 13)));
    if (pos < DEPTH_C) sbuf[bin * DEPTH_C + pos] = e;
    else {                                       // rare (Poisson tail): direct
        unsigned p = atomicAdd(&g_ccur[bin], 1u);
        if (p < CCAP) g_cbucket[(size_t)bin * CCAP + p] = e;
    }
}

__global__ void __launch_bounds__(1024, 2) k_coarse(const float* __restrict__ vals,
                                                    const int*   __restrict__ rows,
                                                    const int*   __restrict__ cols,
                                                    int nnz, int csz) {
    extern __shared__ float2 sbuf[];             // NCB * DEPTH_C
    __shared__ unsigned scnt[NCB];
    __shared__ unsigned sbase[NCB];
    int tid  = threadIdx.x;
    int w    = tid >> 5;
    int lane = tid & 31;
    int start = blockIdx.x * csz;
    int end   = min(nnz, start + csz);

    for (int base = start; base < end; base += TC) {
        if (tid < NCB) scnt[tid] = 0;
        __syncthreads();

        int i0 = base + tid * 8;
        if (base + TC <= end) {
            // two 4-wide groups (lower register pressure than one 8-wide)
            float4 v0 = *(const float4*)(vals + i0);
            int4   r0 = *(const int4*)(rows + i0);
            int4   c0 = *(const int4*)(cols + i0);
            cplace(v0.x, r0.x, c0.x, scnt, sbuf);
            cplace(v0.y, r0.y, c0.y, scnt, sbuf);
            cplace(v0.z, r0.z, c0.z, scnt, sbuf);
            cplace(v0.w, r0.w, c0.w, scnt, sbuf);
            float4 v1 = *(const float4*)(vals + i0 + 4);
            int4   r1 = *(const int4*)(rows + i0 + 4);
            int4   c1 = *(const int4*)(cols + i0 + 4);
            cplace(v1.x, r1.x, c1.x, scnt, sbuf);
            cplace(v1.y, r1.y, c1.y, scnt, sbuf);
            cplace(v1.z, r1.z, c1.z, scnt, sbuf);
            cplace(v1.w, r1.w, c1.w, scnt, sbuf);
        } else {
            for (int k = 0; k < 8; k++) {
                int i = i0 + k;
                if (i < end) cplace(vals[i], rows[i], cols[i], scnt, sbuf);
            }
        }
        __syncthreads();

        // Parallel reservation (one round trip), then coalesced copies.
        if (tid < NCB) {
            unsigned c = min(scnt[tid], (unsigned)DEPTH_C);
            sbase[tid] = c ? atomicAdd(&g_ccur[tid], c) : 0u;
        }
        __syncthreads();

        for (int b = w * 8; b < w * 8 + 8; b++) {
            unsigned cnt = min(scnt[b], (unsigned)DEPTH_C);
            if (cnt == 0) continue;
            size_t dst = (size_t)b * CCAP + sbase[b];
            if (lane < cnt)
                g_cbucket[dst + lane] = sbuf[b * DEPTH_C + lane];
            if (cnt > 32 && lane + 32 < cnt)
                g_cbucket[dst + lane + 32] = sbuf[b * DEPTH_C + lane + 32];
        }
        __syncthreads();
    }
}

// ---------------------------------------------------------------------------
// Kernel 4 (ncu slot): fused refine + gather + epilogue. R11's proven
// bulk-synchronous structure (all 512 threads stage, then all drain),
// grid 512 = (bin, segment); completion counter runs the erf epilogue.
__global__ void __launch_bounds__(512, 4) k_fuse(float* __restrict__ out) {
    extern __shared__ float2 stg[];              // 32 * DEPTH_F
    __shared__ unsigned scnt[32];
    __shared__ unsigned sdone;
    int tid  = threadIdx.x;
    int w    = tid >> 5;
    int lane = tid & 31;
    int half = lane >> 4;
    int b    = lane & 15;
    int cb   = blockIdx.x >> 1;
    int seg  = blockIdx.x & 1;

    int cnt = min(g_ccur[cb], (unsigned)CCAP);
    int s_beg = seg ? (cnt >> 1) : 0;
    int s_end = seg ? cnt : (cnt >> 1);
    const float2* __restrict__ src = g_cbucket + (size_t)cb * CCAP;

    float acc0 = 0.0f, acc1 = 0.0f;              // rows cb*32+2w, +2w+1

    for (int base = s_beg; base < s_end; base += TF) {
        if (tid < 32) scnt[tid] = 0;
        __syncthreads();

        int n = min(TF, s_end - base);
        for (int k = tid; k < n; k += 512) {     // coalesced stream, all threads
            float2 e = src[base + k];
            int rl = (__float_as_int(e.y) >> 13) & 31;
            unsigned pos = atomicAdd(&scnt[rl], 1u);
            if (pos < DEPTH_F) {
                stg[rl * DEPTH_F + pos] = e;
            } else {                             // ~never: direct z accumulation
                int c = __float_as_int(e.y) & 8191;
                float v = e.x;
                const float4* s4 = reinterpret_cast<const float4*>(g_state_T + c * BATCH);
                float4 s0 = s4[0], s1 = s4[1], s2 = s4[2], s3 = s4[3];
                float* zp = g_z + ((cb << 5) | rl) * BATCH;
                red_add_v4(zp + 0,  v * s0.x, v * s0.y, v * s0.z, v * s0.w);
                red_add_v4(zp + 4,  v * s1.x, v * s1.y, v * s1.z, v * s1.w);
                red_add_v4(zp + 8,  v * s2.x, v * s2.y, v * s2.z, v * s2.w);
                red_add_v4(zp + 12, v * s3.x, v * s3.y, v * s3.z, v * s3.w);
            }
        }
        __syncthreads();

        // Drain: warp w -> rows 2w, 2w+1; half-warp = one entry; 8 in flight.
#pragma unroll
        for (int rr = 0; rr < 2; rr++) {
            int rl = (w << 1) | rr;
            int m = min(scnt[rl], (unsigned)DEPTH_F);
            const float2* row = stg + rl * DEPTH_F;
            float acc = 0.0f;
            int j = half;
            for (; j + 14 < m; j += 16) {
                float2 e0 = row[j];
                float2 e1 = row[j + 2];
                float2 e2 = row[j + 4];
                float2 e3 = row[j + 6];
                float2 e4 = row[j + 8];
                float2 e5 = row[j + 10];
                float2 e6 = row[j + 12];
                float2 e7 = row[j + 14];
                float s0 = g_state_T[(__float_as_int(e0.y) & 8191) * BATCH + b];
                float s1 = g_state_T[(__float_as_int(e1.y) & 8191) * BATCH + b];
                float s2 = g_state_T[(__float_as_int(e2.y) & 8191) * BATCH + b];
                float s3 = g_state_T[(__float_as_int(e3.y) & 8191) * BATCH + b];
                float s4 = g_state_T[(__float_as_int(e4.y) & 8191) * BATCH + b];
                float s5 = g_state_T[(__float_as_int(e5.y) & 8191) * BATCH + b];
                float s6 = g_state_T[(__float_as_int(e6.y) & 8191) * BATCH + b];
                float s7 = g_state_T[(__float_as_int(e7.y) & 8191) * BATCH + b];
                acc = fmaf(e0.x, s0, acc);
                acc = fmaf(e1.x, s1, acc);
                acc = fmaf(e2.x, s2, acc);
                acc = fmaf(e3.x, s3, acc);
                acc = fmaf(e4.x, s4, acc);
                acc = fmaf(e5.x, s5, acc);
                acc = fmaf(e6.x, s6, acc);
                acc = fmaf(e7.x, s7, acc);
            }
            for (; j < m; j += 2) {
                float2 e = row[j];
                acc = fmaf(e.x, g_state_T[(__float_as_int(e.y) & 8191) * BATCH + b], acc);
            }
            if (rr) acc1 += acc; else acc0 += acc;
        }
        __syncthreads();
    }

    // Flush 32-row partials into g_z.
    acc0 += __shfl_xor_sync(0xffffffffu, acc0, 16);
    acc1 += __shfl_xor_sync(0xffffffffu, acc1, 16);
    if (lane < BATCH) {
        int r0 = (cb << 5) | (w << 1);
        red_add_f32(g_z + r0 * BATCH + lane, acc0);
        red_add_f32(g_z + (r0 + 1) * BATCH + lane, acc1);
    }
    __syncthreads();

    // Completion counter: last segment-block of the bin runs the epilogue.
    if (tid == 0) {
        __threadfence();
        sdone = atomicAdd(&g_done[cb], 1u);
    }
    __syncthreads();
    if (sdone == NSEG - 1) {
        __threadfence();
        int i = (cb << 9) | tid;                 // bin's 512 outputs (32 rows x 16)
        float z = g_z[i];
        float s = g_state_T[i];                  // = state[b][r]
        int r = i >> 4;
        int bb = i & 15;
        out[bb * N_RES + r] = (1.0f - LEAK) * s + LEAK * erff(z);
    }
}

// ---------------------------------------------------------------------------
extern "C" void kernel_launch(void* const* d_in, const int* in_sizes, int n_in,
                              void* d_out, int out_size) {
    const float* state    = (const float*)d_in[0];
    const float* x        = (const float*)d_in[1];
    const float* res_vals = (const float*)d_in[2];
    const int*   res_rows = (const int*)  d_in[3];
    const int*   res_cols = (const int*)  d_in[4];
    const float* res_bias = (const float*)d_in[5];
    const float* in_vals  = (const float*)d_in[6];
    const int*   in_rows  = (const int*)  d_in[7];
    const int*   in_cols  = (const int*)  d_in[8];
    const float* in_bias  = (const float*)d_in[9];
    float* out = (float*)d_out;

    int res_nnz = in_sizes[2];
    int in_nnz  = in_sizes[6];
    int csz = ((res_nnz + NCH - 1) / NCH + 7) & ~7;

    static int smem_set = 0;
    if (!smem_set) {
        cudaFuncSetAttribute(k_coarse, cudaFuncAttributeMaxDynamicSharedMemorySize, COARSE_SMEM);
        cudaFuncSetAttribute(k_fuse,   cudaFuncAttributeMaxDynamicSharedMemorySize, FUSE_SMEM);
        smem_set = 1;
    }

    // Launch order: slot 4 (ncu capture) = k_fuse.
    k_init<<<(N_RES * BATCH + 255) / 256, 256>>>(state, x, res_bias, in_bias);

    k_in_spmm<<<(in_nnz + 255) / 256, 256>>>(in_vals, in_rows, in_cols, in_nnz);

    k_coarse<<<NCH, 1024, COARSE_SMEM>>>(res_vals, res_rows, res_cols, res_nnz, csz);

    k_fuse<<<NCB * NSEG, 512, FUSE_SMEM>>>(out);
}